// round 12
// baseline (speedup 1.0000x reference)
#include <cuda_runtime.h>
#include <math.h>

#define BB 8192
#define NN 4096
#define WBINS 1000
#define LSTRIDE 101        // L_CUTOFF + 1, row stride of sine_terms
#define LL 12              // truncated series: for sigma>0.6, term l=12 < 1e-9 rel
#define GRAD_GAUSS_THRES 0.6f
#define GPB 4              // batches per block
#define THREADS 256
#define SINE_STRIDE 1024   // padded row stride of g_sineT (zeros beyond WBINS)
#define TABROW 1002        // floats per table row (1001 used)

__device__ float g_sineT[LL * SINE_STRIDE];

// ---------------------------------------------------------------------------
// Kernel 0: transpose first LL columns of sine_terms.
// One thread per (l, w): reads only the needed 12 cols/row (64 KB of sectors
// vs 404 KB whole-matrix), writes fully coalesced. Tail threads zero the pad.
// ---------------------------------------------------------------------------
__global__ void transpose_kernel(const float* __restrict__ sine_terms) {
    int idx = blockIdx.x * blockDim.x + threadIdx.x;   // 0 .. LL*1024-1
    int l = idx >> 10;
    int w = idx & (SINE_STRIDE - 1);
    float v = 0.0f;
    if (w < WBINS) v = __ldg(&sine_terms[w * LSTRIDE + l]);
    g_sineT[idx] = v;
}

// ---------------------------------------------------------------------------
// Fused kernel. Per block: build 4 batches' single-float v-tables in SMEM,
//   u[idx] = pdf_pad[idx] * bw / (pdf_pad[idx+1] - pdf_pad[idx])   ( = left/grad )
//   v[idx] = u[idx] - (idx + 0.5) * bw                 (center folded in)
// from the truncated Legendre series (unnormalized pdf — normalization cancels),
// then evaluate 4*4096 omegas as  out = 1 / (v[idx] + w)
// == reference's grad_pdf / pdf_accurate. grad==0 -> v=inf -> out=0 (matches).
// pdf_pad = [pdf[0], pdf[0..999], pdf[998]].
// idx = floor(fma(w, inv_bw, 0.5)) <= 1000 always (w < pi_fp32), no clamp.
// Phase 2: single pass over batches; bins in 2 segments of 500.
// ---------------------------------------------------------------------------
__global__ __launch_bounds__(THREADS, 7)
void fused_kernel(const float* __restrict__ sigmas,
                  const float* __restrict__ omegas,
                  const float* __restrict__ omega_grid,
                  float* __restrict__ out) {
    __shared__ float  s_tab[GPB][TABROW];            // ~16 KB
    __shared__ __align__(16) float s_expT[LL][GPB];  // transposed series weights
    __shared__ float  s_edge[8][GPB];                // per-warp boundary pdf values
    __shared__ float  s_cross[GPB];                  // pdf[511] (segment boundary)
    __shared__ float2 s_par[GPB];

    const int tid  = threadIdx.x;
    const int lane = tid & 31;
    const int wid  = tid >> 5;
    const int base = blockIdx.x * GPB;

    const float bw     = __ldg(&omega_grid[1]) - __ldg(&omega_grid[0]);
    const float inv_bw = 1.0f / bw;

    // ---- phase 1: per-batch params + series weights -------------------------
    if (tid < GPB) {
        float sg = sigmas[base + tid];
        s_par[tid] = make_float2(-1.0f / (sg * sg),
                                 (sg > GRAD_GAUSS_THRES) ? 1.0f : 0.0f);
    }
    if (tid < GPB * LL) {
        int l = tid >> 2;
        int g = tid & (GPB - 1);
        float sg = sigmas[base + g];
        s_expT[l][g] = expf(-0.5f * (float)(l * (l + 1)) * (sg * sg));
    }
    __syncthreads();

    // ---- phase 2: series, single pass over 4 batches, 2 bin-segments --------
    #pragma unroll 1
    for (int seg = 0; seg < 2; seg++) {
        const int j = tid + 256 * seg;        // bin-pair index: bins 2j, 2j+1
        float a0[GPB], a1[GPB];
        #pragma unroll
        for (int g = 0; g < GPB; g++) { a0[g] = 0.0f; a1[g] = 0.0f; }

        #pragma unroll
        for (int l = LL - 1; l >= 0; l--) {   // small terms first
            float2 sv = *reinterpret_cast<const float2*>(
                            &g_sineT[l * SINE_STRIDE + 2 * j]);
            float4 ev = *reinterpret_cast<const float4*>(&s_expT[l][0]);
            a0[0] = fmaf(ev.x, sv.x, a0[0]);  a1[0] = fmaf(ev.x, sv.y, a1[0]);
            a0[1] = fmaf(ev.y, sv.x, a0[1]);  a1[1] = fmaf(ev.y, sv.y, a1[1]);
            a0[2] = fmaf(ev.z, sv.x, a0[2]);  a1[2] = fmaf(ev.z, sv.y, a1[2]);
            a0[3] = fmaf(ev.w, sv.x, a0[3]);  a1[3] = fmaf(ev.w, sv.y, a1[3]);
        }

        // warp w lane 0 holds pdf[2j] with j = 64w (+256*seg)
        if (lane == 0) {
            #pragma unroll
            for (int g = 0; g < GPB; g++) s_edge[wid][g] = a0[g];
        }
        if (seg == 0 && tid == 255) {          // pdf[511] for entry 512
            #pragma unroll
            for (int g = 0; g < GPB; g++) s_cross[g] = a1[g];
        }
        __syncthreads();

        // n0[g] = pdf[2j+2]
        float n0[GPB];
        #pragma unroll
        for (int g = 0; g < GPB; g++)
            n0[g] = __shfl_down_sync(0xffffffffu, a0[g], 1);
        if (lane == 31 && wid < 7) {
            #pragma unroll
            for (int g = 0; g < GPB; g++) n0[g] = s_edge[wid + 1][g];
        }
        if (j == 499) {                        // entry 1000 right = pdf[998] = a0
            #pragma unroll
            for (int g = 0; g < GPB; g++) n0[g] = a0[g];
        }

        const bool defer   = (seg == 0 && tid == 255);  // entry 512 done by seg1 tid0
        const bool active  = (j < 500);
        const float e = 2.0f * (float)j;

        #pragma unroll
        for (int g = 0; g < GPB; g++) {
            if (s_par[g].y > 0.5f) {
                float* trow = s_tab[g];
                if (active) {
                    trow[2*j+1] = __fdividef(a0[g]*bw, a1[g]-a0[g]) - (e+1.5f)*bw;
                    if (!defer)
                        trow[2*j+2] = __fdividef(a1[g]*bw, n0[g]-a1[g]) - (e+2.5f)*bw;
                }
                if (seg == 0 && tid == 0)
                    trow[0] = __int_as_float(0x7f800000);   // grad=0 -> +inf
                if (seg == 1 && tid == 0)                   // entry 512
                    trow[512] = __fdividef(s_cross[g]*bw, a0[g]-s_cross[g]) - 512.5f*bw;
            }
        }
        __syncthreads();   // protects s_edge/s_cross reuse + table visibility
    }

    // ---- phase 3: 4 rows fully unrolled; regs allow next-row LDG hoisting ----
    const float4* om4  = reinterpret_cast<const float4*>(omegas)
                         + (size_t)blockIdx.x * (GPB * NN / 4);
    float4*       out4 = reinterpret_cast<float4*>(out)
                         + (size_t)blockIdx.x * (GPB * NN / 4);

    #pragma unroll
    for (int bl = 0; bl < GPB; bl++) {
        const int i0 = bl * (NN / 4) + tid;            // NN/4 = 1024 = 4*THREADS
        float2 p = s_par[bl];
        float4 m0 = __ldcs(om4 + i0);
        float4 m1 = __ldcs(om4 + i0 + THREADS);
        float4 m2 = __ldcs(om4 + i0 + 2 * THREADS);
        float4 m3 = __ldcs(om4 + i0 + 3 * THREADS);
        if (p.y > 0.5f) {
            const float* row = s_tab[bl];
            float4 r;
            #pragma unroll
            for (int q = 0; q < 4; q++) {
                float4 om = (q == 0) ? m0 : (q == 1) ? m1 : (q == 2) ? m2 : m3;
                #pragma unroll
                for (int c = 0; c < 4; c++) {
                    float w = (&om.x)[c];
                    int idx = __float2int_rd(fmaf(w, inv_bw, 0.5f));
                    (&r.x)[c] = __fdividef(1.0f, row[idx] + w);
                }
                __stcs(out4 + i0 + q * THREADS, r);
            }
        } else {
            float4 r;
            #pragma unroll
            for (int q = 0; q < 4; q++) {
                float4 om = (q == 0) ? m0 : (q == 1) ? m1 : (q == 2) ? m2 : m3;
                r.x = om.x * p.x; r.y = om.y * p.x;
                r.z = om.z * p.x; r.w = om.w * p.x;
                __stcs(out4 + i0 + q * THREADS, r);
            }
        }
    }
}

// ---------------------------------------------------------------------------
extern "C" void kernel_launch(void* const* d_in, const int* in_sizes, int n_in,
                              void* d_out, int out_size) {
    const float* sigmas     = (const float*)d_in[0];   // [B]
    const float* omegas     = (const float*)d_in[1];   // [B, N]
    const float* omega_grid = (const float*)d_in[2];   // [WBINS]
    const float* sine_terms = (const float*)d_in[4];   // [WBINS, 101]

    transpose_kernel<<<LL * SINE_STRIDE / 256, 256>>>(sine_terms);
    fused_kernel<<<BB / GPB, THREADS>>>(sigmas, omegas, omega_grid, (float*)d_out);
}

// round 13
// speedup vs baseline: 1.0357x; 1.0357x over previous
#include <cuda_runtime.h>
#include <math.h>

#define BB 8192
#define NN 4096
#define WBINS 1000
#define LSTRIDE 101        // L_CUTOFF + 1, row stride of sine_terms
#define LL 12              // truncated series: for sigma>0.6, term l=12 < 1e-9 rel
#define GRAD_GAUSS_THRES 0.6f
#define GPB 4              // batches per block
#define THREADS 256
#define SINE_STRIDE 1024   // padded row stride of g_sineT (zeros beyond WBINS)
#define TABROW 1002        // floats per table row (1001 used)

__device__ float g_sineT[LL * SINE_STRIDE];

// ---------------------------------------------------------------------------
// Kernel 0: transpose first LL columns of sine_terms.
// Coalesced reads over the row-major [WBINS,101] input; scattered writes.
// Block 0's first threads zero the w>=1000 padding. (Fastest measured variant.)
// ---------------------------------------------------------------------------
__global__ void transpose_kernel(const float* __restrict__ sine_terms) {
    int idx = blockIdx.x * blockDim.x + threadIdx.x;
    if (blockIdx.x == 0 && threadIdx.x < LL * (SINE_STRIDE - WBINS)) {
        int l = threadIdx.x / (SINE_STRIDE - WBINS);
        int w = WBINS + threadIdx.x % (SINE_STRIDE - WBINS);
        g_sineT[l * SINE_STRIDE + w] = 0.0f;
    }
    if (idx < WBINS * LSTRIDE) {
        int w = idx / LSTRIDE;
        int l = idx - w * LSTRIDE;
        if (l < LL) g_sineT[l * SINE_STRIDE + w] = sine_terms[idx];
    }
}

// ---------------------------------------------------------------------------
// Fused kernel. Per block: build 4 batches' single-float v-tables in SMEM,
//   u[idx] = pdf_pad[idx] * bw / (pdf_pad[idx+1] - pdf_pad[idx])   ( = left/grad )
//   v[idx] = u[idx] - (idx + 0.5) * bw                 (center folded in)
// from the truncated Legendre series (unnormalized pdf — normalization cancels),
// then evaluate 4*4096 omegas as  out = 1 / (v[idx] + w)
// == reference's grad_pdf / pdf_accurate. grad==0 -> v=inf -> out=0 (matches).
// pdf_pad = [pdf[0], pdf[0..999], pdf[998]].
// idx = floor(fma(w, inv_bw, 0.5)) <= 1000 always (w < pi_fp32), no clamp.
// Phase 3 processes ROWS IN PAIRS with all 8 LDG.128 issued up front (MLP=8)
// — 40 warps/SM x 8 x 128B ~= 41KB in flight, enough to saturate HBM.
// ---------------------------------------------------------------------------
__global__ __launch_bounds__(THREADS, 5)
void fused_kernel(const float* __restrict__ sigmas,
                  const float* __restrict__ omegas,
                  const float* __restrict__ omega_grid,
                  float* __restrict__ out) {
    __shared__ float  s_tab[GPB][TABROW];            // ~16 KB
    __shared__ __align__(16) float s_expT[LL][GPB];  // transposed series weights
    __shared__ float  s_edge[8][GPB];                // per-warp boundary pdf values
    __shared__ float  s_cross[GPB];                  // pdf[511] (segment boundary)
    __shared__ float2 s_par[GPB];

    const int tid  = threadIdx.x;
    const int lane = tid & 31;
    const int wid  = tid >> 5;
    const int base = blockIdx.x * GPB;

    const float bw     = __ldg(&omega_grid[1]) - __ldg(&omega_grid[0]);
    const float inv_bw = 1.0f / bw;

    // ---- phase 1: per-batch params + series weights -------------------------
    if (tid < GPB) {
        float sg = sigmas[base + tid];
        s_par[tid] = make_float2(-1.0f / (sg * sg),
                                 (sg > GRAD_GAUSS_THRES) ? 1.0f : 0.0f);
    }
    if (tid < GPB * LL) {
        int l = tid >> 2;
        int g = tid & (GPB - 1);
        float sg = sigmas[base + g];
        s_expT[l][g] = expf(-0.5f * (float)(l * (l + 1)) * (sg * sg));
    }
    __syncthreads();

    // ---- phase 2: series, single pass over 4 batches, 2 bin-segments --------
    #pragma unroll 1
    for (int seg = 0; seg < 2; seg++) {
        const int j = tid + 256 * seg;        // bin-pair index: bins 2j, 2j+1
        float a0[GPB], a1[GPB];
        #pragma unroll
        for (int g = 0; g < GPB; g++) { a0[g] = 0.0f; a1[g] = 0.0f; }

        #pragma unroll
        for (int l = LL - 1; l >= 0; l--) {   // small terms first
            float2 sv = *reinterpret_cast<const float2*>(
                            &g_sineT[l * SINE_STRIDE + 2 * j]);
            float4 ev = *reinterpret_cast<const float4*>(&s_expT[l][0]);
            a0[0] = fmaf(ev.x, sv.x, a0[0]);  a1[0] = fmaf(ev.x, sv.y, a1[0]);
            a0[1] = fmaf(ev.y, sv.x, a0[1]);  a1[1] = fmaf(ev.y, sv.y, a1[1]);
            a0[2] = fmaf(ev.z, sv.x, a0[2]);  a1[2] = fmaf(ev.z, sv.y, a1[2]);
            a0[3] = fmaf(ev.w, sv.x, a0[3]);  a1[3] = fmaf(ev.w, sv.y, a1[3]);
        }

        // warp w lane 0 holds pdf[2j] with j = 64w (+256*seg)
        if (lane == 0) {
            #pragma unroll
            for (int g = 0; g < GPB; g++) s_edge[wid][g] = a0[g];
        }
        if (seg == 0 && tid == 255) {          // pdf[511] for entry 512
            #pragma unroll
            for (int g = 0; g < GPB; g++) s_cross[g] = a1[g];
        }
        __syncthreads();

        // n0[g] = pdf[2j+2]
        float n0[GPB];
        #pragma unroll
        for (int g = 0; g < GPB; g++)
            n0[g] = __shfl_down_sync(0xffffffffu, a0[g], 1);
        if (lane == 31 && wid < 7) {
            #pragma unroll
            for (int g = 0; g < GPB; g++) n0[g] = s_edge[wid + 1][g];
        }
        if (j == 499) {                        // entry 1000 right = pdf[998] = a0
            #pragma unroll
            for (int g = 0; g < GPB; g++) n0[g] = a0[g];
        }

        const bool defer   = (seg == 0 && tid == 255);  // entry 512 done by seg1 tid0
        const bool active  = (j < 500);
        const float e = 2.0f * (float)j;

        #pragma unroll
        for (int g = 0; g < GPB; g++) {
            if (s_par[g].y > 0.5f) {
                float* trow = s_tab[g];
                if (active) {
                    trow[2*j+1] = __fdividef(a0[g]*bw, a1[g]-a0[g]) - (e+1.5f)*bw;
                    if (!defer)
                        trow[2*j+2] = __fdividef(a1[g]*bw, n0[g]-a1[g]) - (e+2.5f)*bw;
                }
                if (seg == 0 && tid == 0)
                    trow[0] = __int_as_float(0x7f800000);   // grad=0 -> +inf
                if (seg == 1 && tid == 0)                   // entry 512
                    trow[512] = __fdividef(s_cross[g]*bw, a0[g]-s_cross[g]) - 512.5f*bw;
            }
        }
        __syncthreads();   // protects s_edge/s_cross reuse + table visibility
    }

    // ---- phase 3: row pairs, 8 LDG.128 in flight per warp (MLP=8) -----------
    const float4* om4  = reinterpret_cast<const float4*>(omegas)
                         + (size_t)blockIdx.x * (GPB * NN / 4);
    float4*       out4 = reinterpret_cast<float4*>(out)
                         + (size_t)blockIdx.x * (GPB * NN / 4);

    #pragma unroll
    for (int bp = 0; bp < GPB; bp += 2) {
        const int iA = bp * (NN / 4) + tid;            // NN/4 = 1024 = 4*THREADS
        const int iB = iA + (NN / 4);
        float2 pA = s_par[bp];
        float2 pB = s_par[bp + 1];
        float4 mA0 = __ldcs(om4 + iA);
        float4 mA1 = __ldcs(om4 + iA + THREADS);
        float4 mA2 = __ldcs(om4 + iA + 2 * THREADS);
        float4 mA3 = __ldcs(om4 + iA + 3 * THREADS);
        float4 mB0 = __ldcs(om4 + iB);
        float4 mB1 = __ldcs(om4 + iB + THREADS);
        float4 mB2 = __ldcs(om4 + iB + 2 * THREADS);
        float4 mB3 = __ldcs(om4 + iB + 3 * THREADS);

        // ---- row A ----
        if (pA.y > 0.5f) {
            const float* row = s_tab[bp];
            float4 r;
            #pragma unroll
            for (int q = 0; q < 4; q++) {
                float4 om = (q == 0) ? mA0 : (q == 1) ? mA1 : (q == 2) ? mA2 : mA3;
                #pragma unroll
                for (int c = 0; c < 4; c++) {
                    float w = (&om.x)[c];
                    int idx = __float2int_rd(fmaf(w, inv_bw, 0.5f));
                    (&r.x)[c] = __fdividef(1.0f, row[idx] + w);
                }
                __stcs(out4 + iA + q * THREADS, r);
            }
        } else {
            float4 r;
            #pragma unroll
            for (int q = 0; q < 4; q++) {
                float4 om = (q == 0) ? mA0 : (q == 1) ? mA1 : (q == 2) ? mA2 : mA3;
                r.x = om.x * pA.x; r.y = om.y * pA.x;
                r.z = om.z * pA.x; r.w = om.w * pA.x;
                __stcs(out4 + iA + q * THREADS, r);
            }
        }

        // ---- row B ----
        if (pB.y > 0.5f) {
            const float* row = s_tab[bp + 1];
            float4 r;
            #pragma unroll
            for (int q = 0; q < 4; q++) {
                float4 om = (q == 0) ? mB0 : (q == 1) ? mB1 : (q == 2) ? mB2 : mB3;
                #pragma unroll
                for (int c = 0; c < 4; c++) {
                    float w = (&om.x)[c];
                    int idx = __float2int_rd(fmaf(w, inv_bw, 0.5f));
                    (&r.x)[c] = __fdividef(1.0f, row[idx] + w);
                }
                __stcs(out4 + iB + q * THREADS, r);
            }
        } else {
            float4 r;
            #pragma unroll
            for (int q = 0; q < 4; q++) {
                float4 om = (q == 0) ? mB0 : (q == 1) ? mB1 : (q == 2) ? mB2 : mB3;
                r.x = om.x * pB.x; r.y = om.y * pB.x;
                r.z = om.z * pB.x; r.w = om.w * pB.x;
                __stcs(out4 + iB + q * THREADS, r);
            }
        }
    }
}

// ---------------------------------------------------------------------------
extern "C" void kernel_launch(void* const* d_in, const int* in_sizes, int n_in,
                              void* d_out, int out_size) {
    const float* sigmas     = (const float*)d_in[0];   // [B]
    const float* omegas     = (const float*)d_in[1];   // [B, N]
    const float* omega_grid = (const float*)d_in[2];   // [WBINS]
    const float* sine_terms = (const float*)d_in[4];   // [WBINS, 101]

    transpose_kernel<<<(WBINS * LSTRIDE + 255) / 256, 256>>>(sine_terms);
    fused_kernel<<<BB / GPB, THREADS>>>(sigmas, omegas, omega_grid, (float*)d_out);
}